// round 14
// baseline (speedup 1.0000x reference)
#include <cuda_runtime.h>
#include <math_constants.h>

// ---------------------------------------------------------------------------
// MultiTaskLossWrapper — warp-specialized block-local, G=148 (R13 base).
// Warps 0-15  (pair role): load age/grade/h3, build 4 lists, run pair tiles.
// Warps 16-31 (cox role) : vectorized load surv/h3/h1/cen, exp into s_sp,
//                          cox sweep; censor staged in s_sp.w.
// One full-block sync publishes s_sp + counts; roles then use named barriers.
// Last block (atomic ticket) combines partials in fixed order. Deterministic.
// Inputs: 0 hazard3d f32[B], 1 hazard1d f32[B], 2 survtime f32[B],
//         3 censor f32[B], 4 vars_ f32[4], 5 beta1, 6 beta2,
//         7 age i32[B], 8 grade i32[B].  Output: f32[1]
// ---------------------------------------------------------------------------

#define G 148
#define T 1024
#define NPW 16                  // pair warps
#define TOTP (G * NPW)
#define BMAX 4096
#define EPB 28                  // rows per block
#define NROW 7                  // rows per cox warp group
#define NKP 8                   // elements per pair-warp lane
#define LISTPAD (BMAX + 128)

__constant__ float c_risk_table[9] = {1.0f, 1.0f, 0.91f, 1.12f, 1.71f,
                                      2.41f, 3.27f, 5.18f, 8.44f};

__device__ float2 g_coxp[G];
__device__ float4 g_pairp[G];
__device__ int    g_ticket = 0;    // finisher resets -> replay-safe

__device__ __forceinline__ float warpSumF(float v) {
#pragma unroll
    for (int o = 16; o; o >>= 1) v += __shfl_xor_sync(0xffffffffu, v, o);
    return v;
}
__device__ __forceinline__ void barHalf(int id) {
    asm volatile("bar.sync %0, %1;" :: "r"(id), "r"(512) : "memory");
}

__global__ void __launch_bounds__(T)
fused_kernel(const float* __restrict__ h3, const float* __restrict__ h1,
             const float* __restrict__ surv, const float* __restrict__ cen,
             const float* __restrict__ vars,
             const float* __restrict__ b1p, const float* __restrict__ b2p,
             const int* __restrict__ age, const int* __restrict__ grade,
             float* __restrict__ out, int B) {
    extern __shared__ float sm[];
    float4* s_sp  = (float4*)sm;                           // [BMAX] (surv,e3,e1,cen)
    int2*   s_lpk = (int2*)(sm + 4 * BMAX);                // [LISTPAD] (meta,h bits)

    __shared__ int   s_gc[4][128];
    __shared__ int   s_tot[4];
    __shared__ float tabL[81], tabH[81];
    __shared__ float s_p3[EPB][4], s_p1[EPB][4];
    __shared__ float s_pr[4][NPW];
    __shared__ float s_fin[6][5];
    __shared__ int   s_last;

    const int b = blockIdx.x, tid = threadIdx.x;
    const int w = tid >> 5, lane = tid & 31;
    const bool isPair = (w < NPW);

    // ---- alpha tables (pair half threads 0-161) ---------------------------
    if (tid < 162) {
        bool isL = tid < 81;
        int i = isL ? tid : tid - 81;
        float bb = isL ? *b1p : *b2p;
        float d = (c_risk_table[i % 9] - c_risk_table[i / 9]) * 0.125f;
        float al = __fdividef(d, 1.0f + __expf(-bb * d));
        if (isL) tabL[i] = al; else tabH[i] = al;
    }

    // ---- phase A: role-split loading --------------------------------------
    unsigned mlpack = 0u;
    unsigned bkpack = 0u;
    unsigned mymask[NKP];
    float    hv[NKP];

    if (isPair) {
        // pair warps: age/grade/h3 for 256 elements each; ballots
#pragma unroll
        for (int k = 0; k < NKP; k++) {
            int e = w * 256 + k * 32 + lane;
            bool valid = (e < B);
            int a_ = valid ? age[e]   : -1;
            int g_ = valid ? grade[e] : -1;
            hv[k]  = valid ? h3[e]    : 0.0f;
            int ml = -1;
            if (g_ == 0)                 ml = (a_ < 40) ? 0 : 1;
            else if (g_ == 1 || g_ == 2) ml = (a_ < 65) ? 2 : 3;
            int bkt = a_ / 10; bkt = bkt < 0 ? 0 : (bkt > 8 ? 8 : bkt);
            mlpack |= (unsigned)(ml + 1) << (3 * k);
            bkpack |= (unsigned)bkt << (4 * k);
            mymask[k] = 0u;
#pragma unroll
            for (int l = 0; l < 4; l++) {
                unsigned mk = __ballot_sync(0xffffffffu, ml == l);
                if (ml == l) mymask[k] = mk;
                if (lane == 0) s_gc[l][w * NKP + k] = __popc(mk);
            }
        }
    } else {
        // cox warps: vectorized staging — thread owns 8 contiguous elements
        const int ct = tid - NPW * 32;            // 0..511
        const int eb = ct * 8;
        if (eb + 7 < B) {
#pragma unroll
            for (int q = 0; q < 2; q++) {
                float4 a = *(const float4*)(surv + eb + q * 4);
                float4 c = *(const float4*)(h3   + eb + q * 4);
                float4 d = *(const float4*)(h1   + eb + q * 4);
                float4 z = *(const float4*)(cen  + eb + q * 4);
                s_sp[eb + q * 4 + 0] = make_float4(a.x, __expf(c.x), __expf(d.x), z.x);
                s_sp[eb + q * 4 + 1] = make_float4(a.y, __expf(c.y), __expf(d.y), z.y);
                s_sp[eb + q * 4 + 2] = make_float4(a.z, __expf(c.z), __expf(d.z), z.z);
                s_sp[eb + q * 4 + 3] = make_float4(a.w, __expf(c.w), __expf(d.w), z.w);
            }
        } else {
#pragma unroll
            for (int q = 0; q < 8; q++) {
                int e = eb + q;
                if (e < BMAX) {
                    if (e < B)
                        s_sp[e] = make_float4(surv[e], __expf(h3[e]),
                                              __expf(h1[e]), cen[e]);
                    else
                        s_sp[e] = make_float4(-CUDART_INF_F, 0.0f, 0.0f, 0.0f);
                }
            }
        }
    }
    __syncthreads();   // s_sp + group counts + tables published

    if (isPair) {
        // ---- pair half: scan, scatter, pads, tiles ------------------------
        if (w < 4) {
            int l = w;
            int g0 = lane * 4;
            int v0 = s_gc[l][g0], v1 = s_gc[l][g0 + 1];
            int v2 = s_gc[l][g0 + 2], v3 = s_gc[l][g0 + 3];
            int ls = v0 + v1 + v2 + v3;
            int x = ls;
#pragma unroll
            for (int o = 1; o < 32; o <<= 1) {
                int y = __shfl_up_sync(0xffffffffu, x, o);
                if (lane >= o) x += y;
            }
            int base = x - ls;
            s_gc[l][g0]     = base;
            s_gc[l][g0 + 1] = base + v0;
            s_gc[l][g0 + 2] = base + v0 + v1;
            s_gc[l][g0 + 3] = base + v0 + v1 + v2;
            if (lane == 31) s_tot[l] = x;
        }
        barHalf(1);

        // all pair threads compute offsets locally (no extra barrier)
        const int n0 = s_tot[0], n1 = s_tot[1], n2 = s_tot[2], n3 = s_tot[3];
        int off[5];
        off[0] = 0;
        off[1] = (n0 + 31) & ~31;
        off[2] = off[1] + ((n1 + 31) & ~31);
        off[3] = off[2] + ((n2 + 31) & ~31);
        off[4] = off[3] + ((n3 + 31) & ~31);

#pragma unroll
        for (int k = 0; k < NKP; k++) {
            int ml = (int)((mlpack >> (3 * k)) & 7u) - 1;
            if (ml >= 0) {
                int e = w * 256 + k * 32 + lane;
                int bkt = (int)((bkpack >> (4 * k)) & 15u);
                int pos = off[ml] + s_gc[ml][w * NKP + k]
                        + __popc(mymask[k] & ((1u << lane) - 1u));
                s_lpk[pos] = make_int2((e << 4) | bkt, __float_as_int(hv[k]));
            }
        }
#pragma unroll
        for (int l = 0; l < 4; l++) {
            int nl = s_tot[l];
            int sent = (l == 0 || l == 2) ? 0x7FFFFFF0 : -16;
            for (int i = off[l] + nl + tid; i < off[l + 1]; i += 512) {
                s_lpk[i] = make_int2(sent, 0);
            }
        }
        barHalf(1);   // lists complete

        const int uL = (n0 + 31) >> 5, vL = (n1 + 31) >> 5;
        const int uH = (n2 + 31) >> 5, vH = (n3 + 31) >> 5;
        const int NTL = uL * vL, NT = NTL + uH * vH;
        float aS0 = 0.f, aC0 = 0.f, aS1 = 0.f, aC1 = 0.f;
        const int gw = b * NPW + w;

        for (int t = gw; t < NT; t += TOTP) {
            int prob, lu, hvv, lo, ho, nHigh;
            const float* tab;
            if (t < NTL) {
                prob = 0; lu = t / vL; hvv = t - lu * vL;
                lo = off[0]; ho = off[1]; nHigh = n1; tab = tabL;
            } else {
                int tt = t - NTL;
                prob = 1; lu = tt / vH; hvv = tt - lu * vH;
                lo = off[2]; ho = off[3]; nHigh = n3; tab = tabH;
            }
            int lowMin = s_lpk[lo + lu * 32].x >> 4;
            int hlast = hvv * 32 + 31; if (hlast > nHigh - 1) hlast = nHigh - 1;
            int highMax = s_lpk[ho + hlast].x >> 4;
            if (highMax < lowMin) continue;

            int2 pkl = s_lpk[lo + lu * 32 + lane];
            int idxi = pkl.x >> 4;
            int rowoff = (pkl.x & 15) * 9;
            float hi = __int_as_float(pkl.y);
            int hbase = ho + hvv * 32;
            float s = 0.0f, c = 0.0f;
#pragma unroll 4
            for (int jj = 0; jj < 32; jj++) {
                int2 pkh = s_lpk[hbase + jj];        // uniform broadcast
                if ((pkh.x >> 4) > idxi) {
                    float alpha = tab[rowoff + (pkh.x & 15)];
                    float xv = alpha * (hi - __int_as_float(pkh.y));
                    // |xv| <= ~9 -> direct softplus is safe in fp32
                    s += __logf(1.0f + __expf(xv));
                    c += 1.0f;
                }
            }
            if (prob == 0) { aS0 += s; aC0 += c; }
            else           { aS1 += s; aC1 += c; }
        }

        aS0 = warpSumF(aS0); aC0 = warpSumF(aC0);
        aS1 = warpSumF(aS1); aC1 = warpSumF(aC1);
        if (lane == 0) {
            s_pr[0][w] = aS0; s_pr[1][w] = aC0;
            s_pr[2][w] = aS1; s_pr[3][w] = aC1;
        }
        barHalf(1);
        if (tid == 0) {
            float a = 0.f, bb = 0.f, c = 0.f, d = 0.f;
#pragma unroll
            for (int k = 0; k < NPW; k++) {
                a += s_pr[0][k]; bb += s_pr[1][k];
                c += s_pr[2][k]; d  += s_pr[3][k];
            }
            g_pairp[b] = make_float4(a, bb, c, d);
        }
    } else {
        // ---- cox half: sweep (4 row-groups x 4 chunks of 1024) ------------
        const int wc = w - NPW;
        const int rg = wc & 3, cc = wc >> 2;
        const int rbase = b * EPB + rg * NROW;
        float si[NROW], a3[NROW], a1[NROW];
#pragma unroll
        for (int k = 0; k < NROW; k++) {
            int r = rbase + k;
            si[k] = (r < B) ? s_sp[r].x : CUDART_INF_F;
            a3[k] = 0.0f; a1[k] = 0.0f;
        }
        const int cb = cc * 1024 + lane;
#pragma unroll 4
        for (int it = 0; it < 32; it++) {
            float4 p = s_sp[cb + it * 32];     // single LDS.128
#pragma unroll
            for (int k = 0; k < NROW; k++) {
                if (p.x >= si[k]) { a3[k] += p.y; a1[k] += p.z; }
            }
        }
#pragma unroll
        for (int k = 0; k < NROW; k++) {
            a3[k] = warpSumF(a3[k]);
            a1[k] = warpSumF(a1[k]);
            if (lane == 0) {
                s_p3[rg * NROW + k][cc] = a3[k];
                s_p1[rg * NROW + k][cc] = a1[k];
            }
        }
        barHalf(2);
        if (w == NPW) {
            float c3 = 0.0f, c1 = 0.0f;
            if (lane < EPB) {
                int r = b * EPB + lane;
                if (r < B) {
                    float t3 = s_p3[lane][0] + s_p3[lane][1]
                             + s_p3[lane][2] + s_p3[lane][3];
                    float t1 = s_p1[lane][0] + s_p1[lane][1]
                             + s_p1[lane][2] + s_p1[lane][3];
                    float4 q = s_sp[r];                  // cen staged in .w
                    c3 = q.w * __logf(__fdividef(q.y, t3));
                    c1 = q.w * __logf(__fdividef(q.z, t1));
                }
            }
            c3 = warpSumF(c3);
            c1 = warpSumF(c1);
            if (lane == 0) g_coxp[b] = make_float2(c3, c1);
        }
    }

    // ---- ticket: last block combines in fixed order -----------------------
    __syncthreads();
    if (tid == 0) {
        __threadfence();
        int old = atomicAdd(&g_ticket, 1);
        s_last = (old == G - 1) ? 1 : 0;
    }
    __syncthreads();
    if (s_last) {
        if (tid == 0) { g_ticket = 0; __threadfence(); }
        float a0 = 0.f, a1 = 0.f, a2 = 0.f, a3 = 0.f, a4 = 0.f, a5 = 0.f;
        if (tid < G) {
            float2 cp = __ldcg(&g_coxp[tid]);
            float4 pp = __ldcg(&g_pairp[tid]);
            a0 = cp.x; a1 = cp.y;
            a2 = pp.x; a3 = pp.y; a4 = pp.z; a5 = pp.w;
        }
        a0 = warpSumF(a0); a1 = warpSumF(a1); a2 = warpSumF(a2);
        a3 = warpSumF(a3); a4 = warpSumF(a4); a5 = warpSumF(a5);
        if (lane == 0 && w < 5) {
            s_fin[0][w] = a0; s_fin[1][w] = a1; s_fin[2][w] = a2;
            s_fin[3][w] = a3; s_fin[4][w] = a4; s_fin[5][w] = a5;
        }
        __syncthreads();
        if (tid == 0) {
            float s0 = 0.f, s1 = 0.f, s2 = 0.f, s3 = 0.f, s4 = 0.f, s5 = 0.f;
#pragma unroll
            for (int k = 0; k < 5; k++) {
                s0 += s_fin[0][k]; s1 += s_fin[1][k]; s2 += s_fin[2][k];
                s3 += s_fin[3][k]; s4 += s_fin[4][k]; s5 += s_fin[5][k];
            }
            float invB = 1.0f / (float)B;
            float loss3d = -s0 * invB;
            float loss1d = -s1 * invB;
            float lgg = (s3 > 0.5f) ? (s2 / s3) : 0.0f;
            float hgg = (s5 > 0.5f) ? (s4 / s5) : 0.0f;
            float losscli = lgg + hgg;
            float v0 = vars[0], v2 = vars[2], v3 = vars[3];
            out[0] = 0.5f * loss3d / (v0 * v0) + logf(v0)
                   + 0.5f * loss1d / (v2 * v2) + logf(v2)
                   + 0.5f * losscli / (v3 * v3) + logf(v3);
        }
    }
}

extern "C" void kernel_launch(void* const* d_in, const int* in_sizes, int n_in,
                              void* d_out, int out_size) {
    const float* h3     = (const float*)d_in[0];
    const float* h1     = (const float*)d_in[1];
    const float* surv   = (const float*)d_in[2];
    const float* censor = (const float*)d_in[3];
    const float* vars   = (const float*)d_in[4];
    const float* beta1  = (const float*)d_in[5];
    const float* beta2  = (const float*)d_in[6];
    const int*   age    = (const int*)d_in[7];
    const int*   grade  = (const int*)d_in[8];
    int B = in_sizes[0];

    size_t smem = (size_t)BMAX * sizeof(float4)
                + (size_t)LISTPAD * sizeof(int2);            // ~98KB
    cudaFuncSetAttribute(fused_kernel, cudaFuncAttributeMaxDynamicSharedMemorySize,
                         (int)smem);
    fused_kernel<<<G, T, smem>>>(h3, h1, surv, censor, vars, beta1, beta2,
                                 age, grade, (float*)d_out, B);
}

// round 15
// speedup vs baseline: 1.1364x; 1.1364x over previous
#include <cuda_runtime.h>
#include <math_constants.h>

// ---------------------------------------------------------------------------
// MultiTaskLossWrapper — warp-specialized block-local, G=148 (R13 base).
// Warps 0-15  (pair role): load age/grade/h3, build 4 lists, run pair tiles.
// Warps 16-31 (cox role) : load surv/h3/h1/cen (scalar strided), exp into
//                          s_sp, cox sweep; censor staged in s_sp.w.
// One full-block sync publishes s_sp + counts; roles then use named barriers.
// Last block (atomic ticket) combines partials in fixed order. Deterministic.
// Inputs: 0 hazard3d f32[B], 1 hazard1d f32[B], 2 survtime f32[B],
//         3 censor f32[B], 4 vars_ f32[4], 5 beta1, 6 beta2,
//         7 age i32[B], 8 grade i32[B].  Output: f32[1]
// ---------------------------------------------------------------------------

#define G 148
#define T 1024
#define NPW 16                  // pair warps
#define TOTP (G * NPW)
#define BMAX 4096
#define EPB 28                  // rows per block
#define NROW 7                  // rows per cox warp group
#define NKP 8                   // elements per pair-warp lane
#define LISTPAD (BMAX + 128)

__constant__ float c_risk_table[9] = {1.0f, 1.0f, 0.91f, 1.12f, 1.71f,
                                      2.41f, 3.27f, 5.18f, 8.44f};

__device__ float2 g_coxp[G];
__device__ float4 g_pairp[G];
__device__ int    g_ticket = 0;    // finisher resets -> replay-safe

__device__ __forceinline__ float warpSumF(float v) {
#pragma unroll
    for (int o = 16; o; o >>= 1) v += __shfl_xor_sync(0xffffffffu, v, o);
    return v;
}
__device__ __forceinline__ void barHalf(int id) {
    asm volatile("bar.sync %0, %1;" :: "r"(id), "r"(512) : "memory");
}

__global__ void __launch_bounds__(T)
fused_kernel(const float* __restrict__ h3, const float* __restrict__ h1,
             const float* __restrict__ surv, const float* __restrict__ cen,
             const float* __restrict__ vars,
             const float* __restrict__ b1p, const float* __restrict__ b2p,
             const int* __restrict__ age, const int* __restrict__ grade,
             float* __restrict__ out, int B) {
    extern __shared__ float sm[];
    float4* s_sp  = (float4*)sm;                           // [BMAX] (surv,e3,e1,cen)
    int2*   s_lpk = (int2*)(sm + 4 * BMAX);                // [LISTPAD] (meta,h bits)

    __shared__ int   s_gc[4][128];
    __shared__ int   s_tot[4];
    __shared__ float tabL[81], tabH[81];
    __shared__ float s_p3[EPB][4], s_p1[EPB][4];
    __shared__ float s_pr[4][NPW];
    __shared__ float s_fin[6][5];
    __shared__ int   s_last;

    const int b = blockIdx.x, tid = threadIdx.x;
    const int w = tid >> 5, lane = tid & 31;
    const bool isPair = (w < NPW);

    // ---- alpha tables (pair half threads 0-161) ---------------------------
    if (tid < 162) {
        bool isL = tid < 81;
        int i = isL ? tid : tid - 81;
        float bb = isL ? *b1p : *b2p;
        float d = (c_risk_table[i % 9] - c_risk_table[i / 9]) * 0.125f;
        float al = __fdividef(d, 1.0f + __expf(-bb * d));
        if (isL) tabL[i] = al; else tabH[i] = al;
    }

    // ---- phase A: role-split loading --------------------------------------
    unsigned mlpack = 0u;
    unsigned bkpack = 0u;
    unsigned mymask[NKP];
    float    hv[NKP];

    if (isPair) {
        // pair warps: age/grade/h3 for 256 elements each; ballots
#pragma unroll
        for (int k = 0; k < NKP; k++) {
            int e = w * 256 + k * 32 + lane;
            bool valid = (e < B);
            int a_ = valid ? age[e]   : -1;
            int g_ = valid ? grade[e] : -1;
            hv[k]  = valid ? h3[e]    : 0.0f;
            int ml = -1;
            if (g_ == 0)                 ml = (a_ < 40) ? 0 : 1;
            else if (g_ == 1 || g_ == 2) ml = (a_ < 65) ? 2 : 3;
            int bkt = a_ / 10; bkt = bkt < 0 ? 0 : (bkt > 8 ? 8 : bkt);
            mlpack |= (unsigned)(ml + 1) << (3 * k);
            bkpack |= (unsigned)bkt << (4 * k);
            mymask[k] = 0u;
#pragma unroll
            for (int l = 0; l < 4; l++) {
                unsigned mk = __ballot_sync(0xffffffffu, ml == l);
                if (ml == l) mymask[k] = mk;
                if (lane == 0) s_gc[l][w * NKP + k] = __popc(mk);
            }
        }
    } else {
        // cox warps: scalar strided staging (R13 form) + censor in .w
        const int wc = w - NPW;
#pragma unroll
        for (int k = 0; k < NKP; k++) {
            int e = wc * 256 + k * 32 + lane;
            if (e < B) {
                s_sp[e] = make_float4(surv[e], __expf(h3[e]),
                                      __expf(h1[e]), cen[e]);
            } else {
                s_sp[e] = make_float4(-CUDART_INF_F, 0.0f, 0.0f, 0.0f);
            }
        }
    }
    __syncthreads();   // s_sp + group counts + tables published

    if (isPair) {
        // ---- pair half: scan, scatter, pads, tiles ------------------------
        if (w < 4) {
            int l = w;
            int g0 = lane * 4;
            int v0 = s_gc[l][g0], v1 = s_gc[l][g0 + 1];
            int v2 = s_gc[l][g0 + 2], v3 = s_gc[l][g0 + 3];
            int ls = v0 + v1 + v2 + v3;
            int x = ls;
#pragma unroll
            for (int o = 1; o < 32; o <<= 1) {
                int y = __shfl_up_sync(0xffffffffu, x, o);
                if (lane >= o) x += y;
            }
            int base = x - ls;
            s_gc[l][g0]     = base;
            s_gc[l][g0 + 1] = base + v0;
            s_gc[l][g0 + 2] = base + v0 + v1;
            s_gc[l][g0 + 3] = base + v0 + v1 + v2;
            if (lane == 31) s_tot[l] = x;
        }
        barHalf(1);

        // all pair threads compute offsets locally (no extra barrier)
        const int n0 = s_tot[0], n1 = s_tot[1], n2 = s_tot[2], n3 = s_tot[3];
        int off[5];
        off[0] = 0;
        off[1] = (n0 + 31) & ~31;
        off[2] = off[1] + ((n1 + 31) & ~31);
        off[3] = off[2] + ((n2 + 31) & ~31);
        off[4] = off[3] + ((n3 + 31) & ~31);

#pragma unroll
        for (int k = 0; k < NKP; k++) {
            int ml = (int)((mlpack >> (3 * k)) & 7u) - 1;
            if (ml >= 0) {
                int e = w * 256 + k * 32 + lane;
                int bkt = (int)((bkpack >> (4 * k)) & 15u);
                int pos = off[ml] + s_gc[ml][w * NKP + k]
                        + __popc(mymask[k] & ((1u << lane) - 1u));
                s_lpk[pos] = make_int2((e << 4) | bkt, __float_as_int(hv[k]));
            }
        }
#pragma unroll
        for (int l = 0; l < 4; l++) {
            int nl = s_tot[l];
            int sent = (l == 0 || l == 2) ? 0x7FFFFFF0 : -16;
            for (int i = off[l] + nl + tid; i < off[l + 1]; i += 512) {
                s_lpk[i] = make_int2(sent, 0);
            }
        }
        barHalf(1);   // lists complete

        const int uL = (n0 + 31) >> 5, vL = (n1 + 31) >> 5;
        const int uH = (n2 + 31) >> 5, vH = (n3 + 31) >> 5;
        const int NTL = uL * vL, NT = NTL + uH * vH;
        float aS0 = 0.f, aC0 = 0.f, aS1 = 0.f, aC1 = 0.f;
        const int gw = b * NPW + w;

        for (int t = gw; t < NT; t += TOTP) {
            int prob, lu, hvv, lo, ho, nHigh;
            const float* tab;
            if (t < NTL) {
                prob = 0; lu = t / vL; hvv = t - lu * vL;
                lo = off[0]; ho = off[1]; nHigh = n1; tab = tabL;
            } else {
                int tt = t - NTL;
                prob = 1; lu = tt / vH; hvv = tt - lu * vH;
                lo = off[2]; ho = off[3]; nHigh = n3; tab = tabH;
            }
            int lowMin = s_lpk[lo + lu * 32].x >> 4;
            int hlast = hvv * 32 + 31; if (hlast > nHigh - 1) hlast = nHigh - 1;
            int highMax = s_lpk[ho + hlast].x >> 4;
            if (highMax < lowMin) continue;

            int2 pkl = s_lpk[lo + lu * 32 + lane];
            int idxi = pkl.x >> 4;
            int rowoff = (pkl.x & 15) * 9;
            float hi = __int_as_float(pkl.y);
            int hbase = ho + hvv * 32;
            float s = 0.0f, c = 0.0f;
#pragma unroll 4
            for (int jj = 0; jj < 32; jj++) {
                int2 pkh = s_lpk[hbase + jj];        // uniform broadcast
                if ((pkh.x >> 4) > idxi) {
                    float alpha = tab[rowoff + (pkh.x & 15)];
                    float xv = alpha * (hi - __int_as_float(pkh.y));
                    // |xv| <= ~9 -> direct softplus safe in fp32
                    s += __logf(1.0f + __expf(xv));
                    c += 1.0f;
                }
            }
            if (prob == 0) { aS0 += s; aC0 += c; }
            else           { aS1 += s; aC1 += c; }
        }

        aS0 = warpSumF(aS0); aC0 = warpSumF(aC0);
        aS1 = warpSumF(aS1); aC1 = warpSumF(aC1);
        if (lane == 0) {
            s_pr[0][w] = aS0; s_pr[1][w] = aC0;
            s_pr[2][w] = aS1; s_pr[3][w] = aC1;
        }
        barHalf(1);
        if (tid == 0) {
            float a = 0.f, bb = 0.f, c = 0.f, d = 0.f;
#pragma unroll
            for (int k = 0; k < NPW; k++) {
                a += s_pr[0][k]; bb += s_pr[1][k];
                c += s_pr[2][k]; d  += s_pr[3][k];
            }
            g_pairp[b] = make_float4(a, bb, c, d);
        }
    } else {
        // ---- cox half: sweep (4 row-groups x 4 chunks of 1024) ------------
        const int wc = w - NPW;
        const int rg = wc & 3, cc = wc >> 2;
        const int rbase = b * EPB + rg * NROW;
        float si[NROW], a3[NROW], a1[NROW];
#pragma unroll
        for (int k = 0; k < NROW; k++) {
            int r = rbase + k;
            si[k] = (r < B) ? s_sp[r].x : CUDART_INF_F;
            a3[k] = 0.0f; a1[k] = 0.0f;
        }
        const int cb = cc * 1024 + lane;
#pragma unroll 4
        for (int it = 0; it < 32; it++) {
            float4 p = s_sp[cb + it * 32];     // single LDS.128
#pragma unroll
            for (int k = 0; k < NROW; k++) {
                if (p.x >= si[k]) { a3[k] += p.y; a1[k] += p.z; }
            }
        }
#pragma unroll
        for (int k = 0; k < NROW; k++) {
            a3[k] = warpSumF(a3[k]);
            a1[k] = warpSumF(a1[k]);
            if (lane == 0) {
                s_p3[rg * NROW + k][cc] = a3[k];
                s_p1[rg * NROW + k][cc] = a1[k];
            }
        }
        barHalf(2);
        if (w == NPW) {
            float c3 = 0.0f, c1 = 0.0f;
            if (lane < EPB) {
                int r = b * EPB + lane;
                if (r < B) {
                    float t3 = s_p3[lane][0] + s_p3[lane][1]
                             + s_p3[lane][2] + s_p3[lane][3];
                    float t1 = s_p1[lane][0] + s_p1[lane][1]
                             + s_p1[lane][2] + s_p1[lane][3];
                    float4 q = s_sp[r];                  // cen staged in .w
                    c3 = q.w * __logf(__fdividef(q.y, t3));
                    c1 = q.w * __logf(__fdividef(q.z, t1));
                }
            }
            c3 = warpSumF(c3);
            c1 = warpSumF(c1);
            if (lane == 0) g_coxp[b] = make_float2(c3, c1);
        }
    }

    // ---- ticket: last block combines in fixed order -----------------------
    __syncthreads();
    if (tid == 0) {
        __threadfence();
        int old = atomicAdd(&g_ticket, 1);
        s_last = (old == G - 1) ? 1 : 0;
    }
    __syncthreads();
    if (s_last) {
        if (tid == 0) { g_ticket = 0; __threadfence(); }
        float a0 = 0.f, a1 = 0.f, a2 = 0.f, a3 = 0.f, a4 = 0.f, a5 = 0.f;
        if (tid < G) {
            float2 cp = __ldcg(&g_coxp[tid]);
            float4 pp = __ldcg(&g_pairp[tid]);
            a0 = cp.x; a1 = cp.y;
            a2 = pp.x; a3 = pp.y; a4 = pp.z; a5 = pp.w;
        }
        a0 = warpSumF(a0); a1 = warpSumF(a1); a2 = warpSumF(a2);
        a3 = warpSumF(a3); a4 = warpSumF(a4); a5 = warpSumF(a5);
        if (lane == 0 && w < 5) {
            s_fin[0][w] = a0; s_fin[1][w] = a1; s_fin[2][w] = a2;
            s_fin[3][w] = a3; s_fin[4][w] = a4; s_fin[5][w] = a5;
        }
        __syncthreads();
        if (tid == 0) {
            float s0 = 0.f, s1 = 0.f, s2 = 0.f, s3 = 0.f, s4 = 0.f, s5 = 0.f;
#pragma unroll
            for (int k = 0; k < 5; k++) {
                s0 += s_fin[0][k]; s1 += s_fin[1][k]; s2 += s_fin[2][k];
                s3 += s_fin[3][k]; s4 += s_fin[4][k]; s5 += s_fin[5][k];
            }
            float invB = 1.0f / (float)B;
            float loss3d = -s0 * invB;
            float loss1d = -s1 * invB;
            float lgg = (s3 > 0.5f) ? (s2 / s3) : 0.0f;
            float hgg = (s5 > 0.5f) ? (s4 / s5) : 0.0f;
            float losscli = lgg + hgg;
            float v0 = vars[0], v2 = vars[2], v3 = vars[3];
            out[0] = 0.5f * loss3d / (v0 * v0) + logf(v0)
                   + 0.5f * loss1d / (v2 * v2) + logf(v2)
                   + 0.5f * losscli / (v3 * v3) + logf(v3);
        }
    }
}

extern "C" void kernel_launch(void* const* d_in, const int* in_sizes, int n_in,
                              void* d_out, int out_size) {
    const float* h3     = (const float*)d_in[0];
    const float* h1     = (const float*)d_in[1];
    const float* surv   = (const float*)d_in[2];
    const float* censor = (const float*)d_in[3];
    const float* vars   = (const float*)d_in[4];
    const float* beta1  = (const float*)d_in[5];
    const float* beta2  = (const float*)d_in[6];
    const int*   age    = (const int*)d_in[7];
    const int*   grade  = (const int*)d_in[8];
    int B = in_sizes[0];

    size_t smem = (size_t)BMAX * sizeof(float4)
                + (size_t)LISTPAD * sizeof(int2);            // ~98KB
    cudaFuncSetAttribute(fused_kernel, cudaFuncAttributeMaxDynamicSharedMemorySize,
                         (int)smem);
    fused_kernel<<<G, T, smem>>>(h3, h1, surv, censor, vars, beta1, beta2,
                                 age, grade, (float*)d_out, B);
}